// round 7
// baseline (speedup 1.0000x reference)
#include <cuda_runtime.h>
#include <math.h>

#define N_NODES 8192
#define N_EDGES 131072
#define T_STEPS 12
#define H 64

// out layout: [0,8192) pred ; [8192, 8192+T*N*H) tds ; then sds
#define OFF_TD 8192
#define OFF_SD 6299648   // 8192 + 12*8192*64
#define NH 524288        // N*H per time plane

// ---------------- scratch (device globals; no allocation allowed) ----------------
__device__ float g_hx[N_NODES*H];
__device__ float g_nx[N_NODES*H];
__device__ float g_S [N_NODES*H];
__device__ float g_R [N_NODES*H];
__device__ float g_sent [N_NODES*H];
__device__ float g_recvd[N_NODES*H];
__device__ float g_he[N_EDGES*H];
__device__ float g_NewN[N_NODES*T_STEPS*H];   // [8192][768] row-major, col = t*64+h
__device__ float g_gl[H];
__device__ float g_cge[H];
__device__ float g_cgn[H];
__device__ float g_esum_part[1024*H];
__device__ float g_nsum_part[512*H];
__device__ float2 g_WE[H*H];   // (W1^T, W4^T)[k][o]  (ee, he)
__device__ float4 g_WA[H*H];   // (W2^T, W5^T, W3^T, W6^T)[k][o]  (S:nx,hx ; R:nx,hx)
__device__ float4 g_WN[H*H];   // (nx, hx, recvd, sent)^T [k][o]
__device__ float  g_WG[3*H*H]; // gru w_hh transposed per gate: [g][k][o]

__device__ __forceinline__ float sigmoidf_(float x){ return 1.f/(1.f+expf(-x)); }

// ---------------- weight packing (runs every launch; deterministic) ----------------
__global__ void prep_kernel(const float* __restrict__ w_eb,
                            const float* __restrict__ w_nb,
                            const float* __restrict__ w_hh)
{
    int idx = blockIdx.x*blockDim.x + threadIdx.x;   // 0..4095
    if (idx >= H*H) return;
    int o = idx & 63, k = idx >> 6;
    // w_eb: [64][448], col blocks: ee(0) nx_s(64) nx_r(128) he(192) hx_s(256) hx_r(320) gl(384)
    g_WE[idx] = make_float2(w_eb[o*448 + k], w_eb[o*448 + 192 + k]);
    g_WA[idx] = make_float4(w_eb[o*448 +  64 + k], w_eb[o*448 + 256 + k],
                            w_eb[o*448 + 128 + k], w_eb[o*448 + 320 + k]);
    // w_nb: [64][320], blocks: nx(0) hx(64) recvd(128) sent(192) gl(256)
    g_WN[idx] = make_float4(w_nb[o*320 + k],       w_nb[o*320 + 64 + k],
                            w_nb[o*320 + 128 + k], w_nb[o*320 + 192 + k]);
    #pragma unroll
    for (int g = 0; g < 3; g++)
        g_WG[g*4096 + idx] = w_hh[(g*64 + o)*64 + k];   // w_hh: [192][64]
}

// ---------------- zero state ----------------
__global__ void zero_kernel()
{
    int stride = gridDim.x*blockDim.x;
    for (int i = blockIdx.x*blockDim.x + threadIdx.x; i < N_EDGES*H; i += stride)
        g_he[i] = 0.f;
    for (int i = blockIdx.x*blockDim.x + threadIdx.x; i < N_NODES*H; i += stride){
        g_hx[i] = 0.f; g_sent[i] = 0.f; g_recvd[i] = 0.f;
    }
}

// ---------------- GRU over T steps + output head -> pred ----------------
__global__ __launch_bounds__(256) void gru_kernel(
    const float* __restrict__ na, const float* __restrict__ w_ih,
    const float* __restrict__ b_ih, const float* __restrict__ b_hh,
    const float* __restrict__ w_lout, const float* __restrict__ b_lout,
    float* __restrict__ out)
{
    __shared__ float h_sh[4][H];
    __shared__ float red[4][H];
    int slot = threadIdx.x >> 6, o = threadIdx.x & 63;
    int node = blockIdx.x*4 + slot;
    h_sh[slot][o] = 0.f;
    float wi_r = w_ih[o], wi_z = w_ih[64+o], wi_n = w_ih[128+o];
    float cr = b_ih[o] + b_hh[o];
    float cz = b_ih[64+o] + b_hh[64+o];
    float bnx = b_ih[128+o], bnh = b_hh[128+o];
    __syncthreads();
    for (int t = 0; t < T_STEPS; t++){
        float x = na[(size_t)t*N_NODES + node];
        float sr = 0.f, sz = 0.f, sn = 0.f;
        #pragma unroll 8
        for (int k = 0; k < H; k++){
            float hk = h_sh[slot][k];
            sr += g_WG[(k<<6)+o]        * hk;
            sz += g_WG[4096+(k<<6)+o]   * hk;
            sn += g_WG[8192+(k<<6)+o]   * hk;
        }
        float r  = sigmoidf_(wi_r*x + cr + sr);
        float z  = sigmoidf_(wi_z*x + cz + sz);
        float nn = tanhf(wi_n*x + bnx + r*(sn + bnh));
        float hv = (1.f - z)*nn + z*h_sh[slot][o];
        __syncthreads();
        h_sh[slot][o] = hv;
        __syncthreads();
    }
    red[slot][o] = w_lout[o]*h_sh[slot][o];
    __syncthreads();
    if (o == 0){
        float s = b_lout[0];
        #pragma unroll 8
        for (int k = 0; k < H; k++) s += red[slot][k];
        out[node] = s;
    }
}

// ---------------- per-step node encode + edge-side node projections ----------------
__global__ __launch_bounds__(256) void kernelA(int t,
    const float* __restrict__ na, const float* __restrict__ w_ne,
    const float* __restrict__ b_ne)
{
    __shared__ float2 x_sh[4][H];
    int slot = threadIdx.x >> 6, o = threadIdx.x & 63;
    float we = w_ne[o], be = b_ne[o];
    for (int it = 0; it < 4; it++){
        int node = it*2048 + blockIdx.x*4 + slot;
        int base = node*64;
        float x  = na[(size_t)t*N_NODES + node];
        float nx = fmaxf(we*x + be, 0.f);
        g_nx[base+o] = nx;
        float hx = g_hx[base+o];
        x_sh[slot][o] = make_float2(nx, hx);
        __syncthreads();
        float aS = 0.f, aR = 0.f;
        #pragma unroll 8
        for (int k = 0; k < H; k++){
            float4 w = g_WA[(k<<6)+o];
            float2 v = x_sh[slot][k];
            aS += w.x*v.x + w.y*v.y;
            aR += w.z*v.x + w.w*v.y;
        }
        g_S[base+o] = aS;
        g_R[base+o] = aR;
        __syncthreads();
    }
}

// ---------------- per-step edge block ----------------
__global__ __launch_bounds__(256) void kernelB(int t,
    const float* __restrict__ ea, const float* __restrict__ w_ee,
    const float* __restrict__ b_ee, const int* __restrict__ eidx)
{
    __shared__ float2 WE_sh[H*H];   // 32 KB
    __shared__ float2 x_sh[8][H];
    __shared__ float  red[256];
    int tid = threadIdx.x;
    for (int i = tid; i < H*H; i += 256) WE_sh[i] = g_WE[i];
    __syncthreads();
    int slot = tid >> 6, o = tid & 63;
    float we = w_ee[o], be = b_ee[o];
    float cg = g_cge[o];
    float esum_loc = 0.f;
    for (int it = 0; it < 16; it++){
        int p  = it*4096 + blockIdx.x*4 + slot;
        int e0 = 2*p, e1 = 2*p+1;
        float a0 = ea[(size_t)t*N_EDGES + e0];
        float a1 = ea[(size_t)t*N_EDGES + e1];
        x_sh[slot*2  ][o] = make_float2(fmaxf(we*a0+be, 0.f), g_he[(size_t)e0*64+o]);
        x_sh[slot*2+1][o] = make_float2(fmaxf(we*a1+be, 0.f), g_he[(size_t)e1*64+o]);
        __syncthreads();
        int s0 = eidx[e0], r0 = eidx[N_EDGES+e0];
        int s1 = eidx[e1], r1 = eidx[N_EDGES+e1];
        float acc0 = cg + g_S[s0*64+o] + g_R[r0*64+o];
        float acc1 = cg + g_S[s1*64+o] + g_R[r1*64+o];
        #pragma unroll 8
        for (int k = 0; k < H; k++){
            float2 w  = WE_sh[(k<<6)+o];
            float2 v0 = x_sh[slot*2  ][k];
            float2 v1 = x_sh[slot*2+1][k];
            acc0 += w.x*v0.x + w.y*v0.y;
            acc1 += w.x*v1.x + w.y*v1.y;
        }
        float n0 = fmaxf(acc0, 0.f), n1 = fmaxf(acc1, 0.f);
        g_he[(size_t)e0*64+o] = n0;
        g_he[(size_t)e1*64+o] = n1;
        atomicAdd(&g_sent [s0*64+o], n0);
        atomicAdd(&g_recvd[r0*64+o], n0);
        atomicAdd(&g_sent [s1*64+o], n1);
        atomicAdd(&g_recvd[r1*64+o], n1);
        esum_loc += n0 + n1;
        __syncthreads();
    }
    red[tid] = esum_loc;
    __syncthreads();
    if (slot == 0)
        g_esum_part[blockIdx.x*64 + o] = red[o] + red[64+o] + red[128+o] + red[192+o];
}

// ---------------- per-step node block ----------------
__global__ __launch_bounds__(256) void kernelC(int t, float* __restrict__ out)
{
    __shared__ float4 x_sh[4][H];
    __shared__ float  red[256];
    int slot = threadIdx.x >> 6, o = threadIdx.x & 63;
    float cg = g_cgn[o];
    float nsum_loc = 0.f;
    for (int it = 0; it < 4; it++){
        int node = it*2048 + blockIdx.x*4 + slot;
        int base = node*64;
        float nx = g_nx[base+o];
        float hx = g_hx[base+o];
        float rc = g_recvd[base+o];
        float sn = g_sent [base+o];
        g_recvd[base+o] = 0.f;   // reset accumulators for next step
        g_sent [base+o] = 0.f;
        x_sh[slot][o] = make_float4(nx, hx, rc, sn);
        __syncthreads();
        float acc = cg;
        #pragma unroll 8
        for (int k = 0; k < H; k++){
            float4 w = g_WN[(k<<6)+o];
            float4 v = x_sh[slot][k];
            acc += w.x*v.x + w.y*v.y + w.z*v.z + w.w*v.w;
        }
        float nn = fmaxf(acc, 0.f);
        g_hx[base+o] = nn;
        g_NewN[(size_t)node*768 + t*64 + o] = nn;
        out[OFF_TD + (size_t)t*NH + base + o] = nn - hx;
        nsum_loc += nn;
        __syncthreads();
    }
    red[threadIdx.x] = nsum_loc;
    __syncthreads();
    if (slot == 0)
        g_nsum_part[blockIdx.x*64 + o] = red[o] + red[64+o] + red[128+o] + red[192+o];
}

// ---------------- per-step global block (+ per-step constants) ----------------
__global__ void kernelD(int init,
    const float* __restrict__ global_attr,
    const float* __restrict__ w_gb, const float* __restrict__ b_gb,
    const float* __restrict__ w_eb, const float* __restrict__ b_eb,
    const float* __restrict__ w_nb, const float* __restrict__ b_nb)
{
    __shared__ float gin[192];
    __shared__ float gnew[64];
    int o = threadIdx.x;  // 64 threads
    if (init){
        gnew[o] = global_attr[o];
    } else {
        float ns = 0.f, es = 0.f;
        for (int b = 0; b < 512;  b++) ns += g_nsum_part[b*64 + o];
        for (int b = 0; b < 1024; b++) es += g_esum_part[b*64 + o];
        gin[o]      = ns * (1.f/N_NODES);
        gin[64+o]   = es * (1.f/N_EDGES);
        gin[128+o]  = g_gl[o];
        __syncthreads();
        float acc = b_gb[o];
        #pragma unroll 4
        for (int k = 0; k < 192; k++) acc += w_gb[o*192+k]*gin[k];
        gnew[o] = fmaxf(acc, 0.f);
    }
    __syncthreads();
    g_gl[o] = gnew[o];
    float ae = b_eb[o], an = b_nb[o];
    #pragma unroll 8
    for (int k = 0; k < H; k++){
        ae += w_eb[o*448 + 384 + k]*gnew[k];
        an += w_nb[o*320 + 256 + k]*gnew[k];
    }
    g_cge[o] = ae;
    g_cgn[o] = an;
}

// ---------------- final batched GEMM: SD = sp_L[8192x8192] @ NewN[8192x768] ----------------
// BM=BN=128, BK=16, 256 threads, 8x8 register tile. Exact-divisible dims, no guards.
__global__ __launch_bounds__(256) void sgemm_kernel(
    const float* __restrict__ A, const float* __restrict__ coeff,
    float* __restrict__ out)
{
    __shared__ float As[16][132];
    __shared__ float Bs[16][128];
    int tid = threadIdx.x;
    int tx = tid & 15, ty = tid >> 4;
    int row0 = blockIdx.y * 128;
    int col0 = blockIdx.x * 128;
    float acc[8][8];
    #pragma unroll
    for (int i = 0; i < 8; i++)
        #pragma unroll
        for (int j = 0; j < 8; j++) acc[i][j] = 0.f;

    for (int k0 = 0; k0 < 8192; k0 += 16){
        #pragma unroll
        for (int l = 0; l < 2; l++){
            int idx = tid + l*256;           // 0..511
            int m = idx >> 2, k4 = (idx & 3) * 4;
            float4 v = *(const float4*)&A[(size_t)(row0+m)*8192 + k0 + k4];
            As[k4+0][m] = v.x; As[k4+1][m] = v.y; As[k4+2][m] = v.z; As[k4+3][m] = v.w;
        }
        #pragma unroll
        for (int l = 0; l < 2; l++){
            int idx = tid + l*256;
            int k = idx >> 5, n4 = (idx & 31) * 4;
            *(float4*)&Bs[k][n4] = *(const float4*)&g_NewN[(size_t)(k0+k)*768 + col0 + n4];
        }
        __syncthreads();
        #pragma unroll
        for (int k = 0; k < 16; k++){
            float a[8], b[8];
            *(float4*)&a[0] = *(float4*)&As[k][ty*8];
            *(float4*)&a[4] = *(float4*)&As[k][ty*8+4];
            *(float4*)&b[0] = *(float4*)&Bs[k][tx*4];        // cols col0+tx*4..+3
            *(float4*)&b[4] = *(float4*)&Bs[k][64 + tx*4];   // cols col0+64+tx*4..+3
            #pragma unroll
            for (int i = 0; i < 8; i++)
                #pragma unroll
                for (int j = 0; j < 8; j++)
                    acc[i][j] += a[i]*b[j];
        }
        __syncthreads();
    }
    float cf = coeff[0];
    #pragma unroll
    for (int i = 0; i < 8; i++){
        int m = row0 + ty*8 + i;
        #pragma unroll
        for (int j = 0; j < 8; j++){
            int c = col0 + ((j < 4) ? (tx*4 + j) : (64 + tx*4 + (j-4)));
            int tp = c >> 6, h = c & 63;
            out[OFF_SD + (size_t)tp*NH + (size_t)m*64 + h] = cf*acc[i][j];
        }
    }
}

// ---------------- launch ----------------
extern "C" void kernel_launch(void* const* d_in, const int* in_sizes, int n_in,
                              void* d_out, int out_size)
{
    (void)in_sizes; (void)n_in; (void)out_size;
    const float* node_attrs  = (const float*)d_in[0];
    const float* edge_attrs  = (const float*)d_in[1];
    const float* global_attr = (const float*)d_in[2];
    const float* sp_L        = (const float*)d_in[3];
    const float* coeff       = (const float*)d_in[4];
    const float* w_edge_enc  = (const float*)d_in[5];
    const float* b_edge_enc  = (const float*)d_in[6];
    const float* w_node_enc  = (const float*)d_in[7];
    const float* b_node_enc  = (const float*)d_in[8];
    const float* w_eb        = (const float*)d_in[9];
    const float* b_eb        = (const float*)d_in[10];
    const float* w_nb        = (const float*)d_in[11];
    const float* b_nb        = (const float*)d_in[12];
    const float* w_gb        = (const float*)d_in[13];
    const float* b_gb        = (const float*)d_in[14];
    const float* gru_w_ih    = (const float*)d_in[15];
    const float* gru_w_hh    = (const float*)d_in[16];
    const float* gru_b_ih    = (const float*)d_in[17];
    const float* gru_b_hh    = (const float*)d_in[18];
    const float* w_lout      = (const float*)d_in[19];
    const float* b_lout      = (const float*)d_in[20];
    const int*   edge_index  = (const int*)d_in[21];
    float* out = (float*)d_out;

    prep_kernel<<<16, 256>>>(w_eb, w_nb, gru_w_hh);
    zero_kernel<<<2048, 256>>>();
    gru_kernel<<<2048, 256>>>(node_attrs, gru_w_ih, gru_b_ih, gru_b_hh,
                              w_lout, b_lout, out);
    kernelD<<<1, 64>>>(1, global_attr, w_gb, b_gb, w_eb, b_eb, w_nb, b_nb);

    for (int t = 0; t < T_STEPS; t++){
        kernelA<<<512, 256>>>(t, node_attrs, w_node_enc, b_node_enc);
        kernelB<<<1024, 256>>>(t, edge_attrs, w_edge_enc, b_edge_enc, edge_index);
        kernelC<<<512, 256>>>(t, out);
        kernelD<<<1, 64>>>(0, global_attr, w_gb, b_gb, w_eb, b_eb, w_nb, b_nb);
    }

    dim3 grid(6, 64);   // 768 cols / 128, 8192 rows / 128
    sgemm_kernel<<<grid, 256>>>(sp_L, coeff, out);
}

// round 9
// speedup vs baseline: 1.1705x; 1.1705x over previous
#include <cuda_runtime.h>
#include <cuda_bf16.h>
#include <math.h>
#include <stdint.h>

#define N_NODES 8192
#define N_EDGES 131072
#define T_STEPS 12
#define H 64

// out layout: [0,8192) pred ; [8192, 8192+T*N*H) tds ; then sds
#define OFF_TD 8192
#define OFF_SD 6299648   // 8192 + 12*8192*64
#define NH 524288        // N*H per time plane

// ---------------- scratch (device globals; no allocation allowed) ----------------
__device__ float g_hx[N_NODES*H];
__device__ float g_nx[N_NODES*H];
__device__ float g_S [N_NODES*H];
__device__ float g_R [N_NODES*H];
__device__ float g_sent [N_NODES*H];
__device__ float g_recvd[N_NODES*H];
__device__ float g_he[N_EDGES*H];
__device__ float g_NewN[N_NODES*T_STEPS*H];   // [8192][768] row-major, col = t*64+h
__device__ float g_gl[H];
__device__ float g_cge[H];
__device__ float g_cgn[H];
__device__ float g_esum_part[1024*H];
__device__ float g_nsum_part[512*H];
__device__ float2 g_WE[H*H];   // (W1^T, W4^T)[k][o]  (ee, he)
__device__ float4 g_WA[H*H];   // (W2^T, W5^T, W3^T, W6^T)[k][o]  (S:nx,hx ; R:nx,hx)
__device__ float4 g_WN[H*H];   // (nx, hx, recvd, sent)^T [k][o]
__device__ float  g_WG[3*H*H]; // gru w_hh transposed per gate: [g][k][o]

// bf16 split operands for the tensor-core GEMM
__device__ __align__(128) __nv_bfloat16 g_Ahi[(size_t)N_NODES*N_NODES];
__device__ __align__(128) __nv_bfloat16 g_Alo[(size_t)N_NODES*N_NODES];
__device__ __align__(128) __nv_bfloat16 g_Bthi[(size_t)768*N_NODES];   // [n][k] = NewN[k][n]
__device__ __align__(128) __nv_bfloat16 g_Btlo[(size_t)768*N_NODES];

__device__ __forceinline__ float sigmoidf_(float x){ return 1.f/(1.f+expf(-x)); }

// ---------------- mma.sync / ldmatrix wrappers (sm_80+ PTX, compiles for compute_103) ----
__device__ __forceinline__ void ldsm_x4(uint32_t &r0, uint32_t &r1, uint32_t &r2, uint32_t &r3,
                                        uint32_t addr){
    asm volatile("ldmatrix.sync.aligned.m8n8.x4.shared.b16 {%0,%1,%2,%3}, [%4];"
                 : "=r"(r0), "=r"(r1), "=r"(r2), "=r"(r3) : "r"(addr));
}
__device__ __forceinline__ void mma_bf16(float* d, const uint32_t* a, uint32_t b0, uint32_t b1){
    asm volatile("mma.sync.aligned.m16n8k16.row.col.f32.bf16.bf16.f32 "
                 "{%0,%1,%2,%3}, {%4,%5,%6,%7}, {%8,%9}, {%0,%1,%2,%3};"
                 : "+f"(d[0]), "+f"(d[1]), "+f"(d[2]), "+f"(d[3])
                 : "r"(a[0]), "r"(a[1]), "r"(a[2]), "r"(a[3]), "r"(b0), "r"(b1));
}
__device__ __forceinline__ uint32_t smem_u32(const void* p){
    uint32_t a;
    asm("{ .reg .u64 t; cvta.to.shared.u64 t, %1; cvt.u32.u64 %0, t; }" : "=r"(a) : "l"(p));
    return a;
}

// ---------------- weight packing ----------------
__global__ void prep_kernel(const float* __restrict__ w_eb,
                            const float* __restrict__ w_nb,
                            const float* __restrict__ w_hh)
{
    int idx = blockIdx.x*blockDim.x + threadIdx.x;   // 0..4095
    if (idx >= H*H) return;
    int o = idx & 63, k = idx >> 6;
    g_WE[idx] = make_float2(w_eb[o*448 + k], w_eb[o*448 + 192 + k]);
    g_WA[idx] = make_float4(w_eb[o*448 +  64 + k], w_eb[o*448 + 256 + k],
                            w_eb[o*448 + 128 + k], w_eb[o*448 + 320 + k]);
    g_WN[idx] = make_float4(w_nb[o*320 + k],       w_nb[o*320 + 64 + k],
                            w_nb[o*320 + 128 + k], w_nb[o*320 + 192 + k]);
    #pragma unroll
    for (int g = 0; g < 3; g++)
        g_WG[g*4096 + idx] = w_hh[(g*64 + o)*64 + k];
}

// ---------------- zero state ----------------
__global__ void zero_kernel()
{
    int stride = gridDim.x*blockDim.x;
    for (int i = blockIdx.x*blockDim.x + threadIdx.x; i < N_EDGES*H; i += stride)
        g_he[i] = 0.f;
    for (int i = blockIdx.x*blockDim.x + threadIdx.x; i < N_NODES*H; i += stride){
        g_hx[i] = 0.f; g_sent[i] = 0.f; g_recvd[i] = 0.f;
    }
}

// ---------------- fp32 -> bf16 hi/lo split of sp_L ----------------
__global__ __launch_bounds__(256) void convA_kernel(const float* __restrict__ A)
{
    size_t i = (size_t)blockIdx.x*256 + threadIdx.x;   // 16,777,216 float4 groups
    float4 v = ((const float4*)A)[i];
    __nv_bfloat16 h0 = __float2bfloat16(v.x), h1 = __float2bfloat16(v.y);
    __nv_bfloat16 h2 = __float2bfloat16(v.z), h3 = __float2bfloat16(v.w);
    __nv_bfloat16 l0 = __float2bfloat16(v.x - __bfloat162float(h0));
    __nv_bfloat16 l1 = __float2bfloat16(v.y - __bfloat162float(h1));
    __nv_bfloat16 l2 = __float2bfloat16(v.z - __bfloat162float(h2));
    __nv_bfloat16 l3 = __float2bfloat16(v.w - __bfloat162float(h3));
    uint2 ph, pl;
    ph.x = (uint32_t)__bfloat16_as_ushort(h0) | ((uint32_t)__bfloat16_as_ushort(h1) << 16);
    ph.y = (uint32_t)__bfloat16_as_ushort(h2) | ((uint32_t)__bfloat16_as_ushort(h3) << 16);
    pl.x = (uint32_t)__bfloat16_as_ushort(l0) | ((uint32_t)__bfloat16_as_ushort(l1) << 16);
    pl.y = (uint32_t)__bfloat16_as_ushort(l2) | ((uint32_t)__bfloat16_as_ushort(l3) << 16);
    ((uint2*)g_Ahi)[i] = ph;
    ((uint2*)g_Alo)[i] = pl;
}

// ---------------- NewN transpose + bf16 hi/lo split ----------------
__global__ __launch_bounds__(256) void convB_kernel()
{
    size_t g = (size_t)blockIdx.x*256 + threadIdx.x;   // 6,291,456
    int n = (int)(g >> 13);
    int node = (int)(g & 8191);
    float x = g_NewN[(size_t)node*768 + n];
    __nv_bfloat16 h = __float2bfloat16(x);
    __nv_bfloat16 l = __float2bfloat16(x - __bfloat162float(h));
    g_Bthi[g] = h;
    g_Btlo[g] = l;
}

// ---------------- GRU over T steps + output head -> pred ----------------
__global__ __launch_bounds__(256) void gru_kernel(
    const float* __restrict__ na, const float* __restrict__ w_ih,
    const float* __restrict__ b_ih, const float* __restrict__ b_hh,
    const float* __restrict__ w_lout, const float* __restrict__ b_lout,
    float* __restrict__ out)
{
    __shared__ float h_sh[4][H];
    __shared__ float red[4][H];
    int slot = threadIdx.x >> 6, o = threadIdx.x & 63;
    int node = blockIdx.x*4 + slot;
    h_sh[slot][o] = 0.f;
    float wi_r = w_ih[o], wi_z = w_ih[64+o], wi_n = w_ih[128+o];
    float cr = b_ih[o] + b_hh[o];
    float cz = b_ih[64+o] + b_hh[64+o];
    float bnx = b_ih[128+o], bnh = b_hh[128+o];
    __syncthreads();
    for (int t = 0; t < T_STEPS; t++){
        float x = na[(size_t)t*N_NODES + node];
        float sr = 0.f, sz = 0.f, sn = 0.f;
        #pragma unroll 8
        for (int k = 0; k < H; k++){
            float hk = h_sh[slot][k];
            sr += g_WG[(k<<6)+o]        * hk;
            sz += g_WG[4096+(k<<6)+o]   * hk;
            sn += g_WG[8192+(k<<6)+o]   * hk;
        }
        float r  = sigmoidf_(wi_r*x + cr + sr);
        float z  = sigmoidf_(wi_z*x + cz + sz);
        float nn = tanhf(wi_n*x + bnx + r*(sn + bnh));
        float hv = (1.f - z)*nn + z*h_sh[slot][o];
        __syncthreads();
        h_sh[slot][o] = hv;
        __syncthreads();
    }
    red[slot][o] = w_lout[o]*h_sh[slot][o];
    __syncthreads();
    if (o == 0){
        float s = b_lout[0];
        #pragma unroll 8
        for (int k = 0; k < H; k++) s += red[slot][k];
        out[node] = s;
    }
}

// ---------------- per-step node encode + edge-side node projections ----------------
__global__ __launch_bounds__(256) void kernelA(int t,
    const float* __restrict__ na, const float* __restrict__ w_ne,
    const float* __restrict__ b_ne)
{
    __shared__ float2 x_sh[4][H];
    int slot = threadIdx.x >> 6, o = threadIdx.x & 63;
    float we = w_ne[o], be = b_ne[o];
    for (int it = 0; it < 4; it++){
        int node = it*2048 + blockIdx.x*4 + slot;
        int base = node*64;
        float x  = na[(size_t)t*N_NODES + node];
        float nx = fmaxf(we*x + be, 0.f);
        g_nx[base+o] = nx;
        float hx = g_hx[base+o];
        x_sh[slot][o] = make_float2(nx, hx);
        __syncthreads();
        float aS = 0.f, aR = 0.f;
        #pragma unroll 8
        for (int k = 0; k < H; k++){
            float4 w = g_WA[(k<<6)+o];
            float2 v = x_sh[slot][k];
            aS += w.x*v.x + w.y*v.y;
            aR += w.z*v.x + w.w*v.y;
        }
        g_S[base+o] = aS;
        g_R[base+o] = aR;
        __syncthreads();
    }
}

// ---------------- per-step edge block ----------------
__global__ __launch_bounds__(256) void kernelB(int t,
    const float* __restrict__ ea, const float* __restrict__ w_ee,
    const float* __restrict__ b_ee, const int* __restrict__ eidx)
{
    __shared__ float2 WE_sh[H*H];   // 32 KB
    __shared__ float2 x_sh[8][H];
    __shared__ float  red[256];
    int tid = threadIdx.x;
    for (int i = tid; i < H*H; i += 256) WE_sh[i] = g_WE[i];
    __syncthreads();
    int slot = tid >> 6, o = tid & 63;
    float we = w_ee[o], be = b_ee[o];
    float cg = g_cge[o];
    float esum_loc = 0.f;
    for (int it = 0; it < 16; it++){
        int p  = it*4096 + blockIdx.x*4 + slot;
        int e0 = 2*p, e1 = 2*p+1;
        float a0 = ea[(size_t)t*N_EDGES + e0];
        float a1 = ea[(size_t)t*N_EDGES + e1];
        x_sh[slot*2  ][o] = make_float2(fmaxf(we*a0+be, 0.f), g_he[(size_t)e0*64+o]);
        x_sh[slot*2+1][o] = make_float2(fmaxf(we*a1+be, 0.f), g_he[(size_t)e1*64+o]);
        __syncthreads();
        int s0 = eidx[e0], r0 = eidx[N_EDGES+e0];
        int s1 = eidx[e1], r1 = eidx[N_EDGES+e1];
        float acc0 = cg + g_S[s0*64+o] + g_R[r0*64+o];
        float acc1 = cg + g_S[s1*64+o] + g_R[r1*64+o];
        #pragma unroll 8
        for (int k = 0; k < H; k++){
            float2 w  = WE_sh[(k<<6)+o];
            float2 v0 = x_sh[slot*2  ][k];
            float2 v1 = x_sh[slot*2+1][k];
            acc0 += w.x*v0.x + w.y*v0.y;
            acc1 += w.x*v1.x + w.y*v1.y;
        }
        float n0 = fmaxf(acc0, 0.f), n1 = fmaxf(acc1, 0.f);
        g_he[(size_t)e0*64+o] = n0;
        g_he[(size_t)e1*64+o] = n1;
        atomicAdd(&g_sent [s0*64+o], n0);
        atomicAdd(&g_recvd[r0*64+o], n0);
        atomicAdd(&g_sent [s1*64+o], n1);
        atomicAdd(&g_recvd[r1*64+o], n1);
        esum_loc += n0 + n1;
        __syncthreads();
    }
    red[tid] = esum_loc;
    __syncthreads();
    if (slot == 0)
        g_esum_part[blockIdx.x*64 + o] = red[o] + red[64+o] + red[128+o] + red[192+o];
}

// ---------------- per-step node block ----------------
__global__ __launch_bounds__(256) void kernelC(int t, float* __restrict__ out)
{
    __shared__ float4 x_sh[4][H];
    __shared__ float  red[256];
    int slot = threadIdx.x >> 6, o = threadIdx.x & 63;
    float cg = g_cgn[o];
    float nsum_loc = 0.f;
    for (int it = 0; it < 4; it++){
        int node = it*2048 + blockIdx.x*4 + slot;
        int base = node*64;
        float nx = g_nx[base+o];
        float hx = g_hx[base+o];
        float rc = g_recvd[base+o];
        float sn = g_sent [base+o];
        g_recvd[base+o] = 0.f;
        g_sent [base+o] = 0.f;
        x_sh[slot][o] = make_float4(nx, hx, rc, sn);
        __syncthreads();
        float acc = cg;
        #pragma unroll 8
        for (int k = 0; k < H; k++){
            float4 w = g_WN[(k<<6)+o];
            float4 v = x_sh[slot][k];
            acc += w.x*v.x + w.y*v.y + w.z*v.z + w.w*v.w;
        }
        float nn = fmaxf(acc, 0.f);
        g_hx[base+o] = nn;
        g_NewN[(size_t)node*768 + t*64 + o] = nn;
        out[OFF_TD + (size_t)t*NH + base + o] = nn - hx;
        nsum_loc += nn;
        __syncthreads();
    }
    red[threadIdx.x] = nsum_loc;
    __syncthreads();
    if (slot == 0)
        g_nsum_part[blockIdx.x*64 + o] = red[o] + red[64+o] + red[128+o] + red[192+o];
}

// ---------------- per-step global block ----------------
__global__ void kernelD(int init,
    const float* __restrict__ global_attr,
    const float* __restrict__ w_gb, const float* __restrict__ b_gb,
    const float* __restrict__ w_eb, const float* __restrict__ b_eb,
    const float* __restrict__ w_nb, const float* __restrict__ b_nb)
{
    __shared__ float gin[192];
    __shared__ float gnew[64];
    int o = threadIdx.x;  // 64 threads
    if (init){
        gnew[o] = global_attr[o];
    } else {
        float ns = 0.f, es = 0.f;
        for (int b = 0; b < 512;  b++) ns += g_nsum_part[b*64 + o];
        for (int b = 0; b < 1024; b++) es += g_esum_part[b*64 + o];
        gin[o]      = ns * (1.f/N_NODES);
        gin[64+o]   = es * (1.f/N_EDGES);
        gin[128+o]  = g_gl[o];
        __syncthreads();
        float acc = b_gb[o];
        #pragma unroll 4
        for (int k = 0; k < 192; k++) acc += w_gb[o*192+k]*gin[k];
        gnew[o] = fmaxf(acc, 0.f);
    }
    __syncthreads();
    g_gl[o] = gnew[o];
    float ae = b_eb[o], an = b_nb[o];
    #pragma unroll 8
    for (int k = 0; k < H; k++){
        ae += w_eb[o*448 + 384 + k]*gnew[k];
        an += w_nb[o*320 + 256 + k]*gnew[k];
    }
    g_cge[o] = ae;
    g_cgn[o] = an;
}

// ---------------- tensor-core GEMM via mma.sync bf16 hi/lo split ----------------
// C = coeff * sp_L @ NewN   with  C ≈ AhiBhi + AloBhi + AhiBlo (fp32 accum).
// CTA tile 128x128, BK=32, 8 warps (4 m x 2 n), warp tile 32x64.
// Smem rows padded to 80B for conflict-free ldmatrix.
#define SROW 80
#define MAT_BYTES (128*SROW)       // 10240
#define STAGE_BYTES (4*MAT_BYTES)  // 40960: Ahi, Alo, Bhi, Blo
#define GSMEM_BYTES (2*STAGE_BYTES)

__global__ __launch_bounds__(256, 2) void tc_gemm_kernel(const float* __restrict__ coeff,
                                                         float* __restrict__ out)
{
    extern __shared__ char smem[];
    const uint32_t uS = smem_u32(smem);
    const int tid = threadIdx.x, lane = tid & 31, wid = tid >> 5;
    const int warp_m = wid & 3, warp_n = wid >> 2;
    const int m0 = blockIdx.y * 128, n0 = blockIdx.x * 128;

    // ---- global load geometry: thread -> (row = tid>>1, 32B chunk pair) ----
    const int lrow = tid >> 1;
    const int cb   = (tid & 1) * 2;          // 16B-chunk index {0,1} or {2,3}
    const __nv_bfloat16* pAh = g_Ahi  + (size_t)(m0 + lrow)*8192 + cb*8;
    const __nv_bfloat16* pAl = g_Alo  + (size_t)(m0 + lrow)*8192 + cb*8;
    const __nv_bfloat16* pBh = g_Bthi + (size_t)(n0 + lrow)*8192 + cb*8;
    const __nv_bfloat16* pBl = g_Btlo + (size_t)(n0 + lrow)*8192 + cb*8;
    const uint32_t sOff = (uint32_t)(lrow*SROW + cb*16);

    // ---- ldmatrix lane offset (shared by A and B tiles) ----
    const uint32_t lmOff = (uint32_t)((((lane >> 3) & 1)*8 + (lane & 7))*SROW
                                      + (lane >> 4)*16);

    float acc[2][8][4];
    #pragma unroll
    for (int i = 0; i < 2; i++)
        #pragma unroll
        for (int j = 0; j < 8; j++)
            #pragma unroll
            for (int v = 0; v < 4; v++) acc[i][j][v] = 0.f;

    // prefetch chunk 0
    uint4 rAh[2], rAl[2], rBh[2], rBl[2];
    #pragma unroll
    for (int j = 0; j < 2; j++){
        rAh[j] = *(const uint4*)(pAh + j*8);
        rAl[j] = *(const uint4*)(pAl + j*8);
        rBh[j] = *(const uint4*)(pBh + j*8);
        rBl[j] = *(const uint4*)(pBl + j*8);
    }

    for (int c = 0; c < 256; c++){
        char* sbuf = smem + (c & 1)*STAGE_BYTES;
        #pragma unroll
        for (int j = 0; j < 2; j++){
            *(uint4*)(sbuf +               sOff + j*16) = rAh[j];
            *(uint4*)(sbuf +   MAT_BYTES + sOff + j*16) = rAl[j];
            *(uint4*)(sbuf + 2*MAT_BYTES + sOff + j*16) = rBh[j];
            *(uint4*)(sbuf + 3*MAT_BYTES + sOff + j*16) = rBl[j];
        }
        __syncthreads();

        if (c < 255){
            size_t k0 = (size_t)(c + 1)*32;
            #pragma unroll
            for (int j = 0; j < 2; j++){
                rAh[j] = *(const uint4*)(pAh + k0 + j*8);
                rAl[j] = *(const uint4*)(pAl + k0 + j*8);
                rBh[j] = *(const uint4*)(pBh + k0 + j*8);
                rBl[j] = *(const uint4*)(pBl + k0 + j*8);
            }
        }

        const uint32_t sb = uS + (uint32_t)((c & 1)*STAGE_BYTES);
        #pragma unroll
        for (int k16 = 0; k16 < 2; k16++){
            const uint32_t ko = k16*32;
            uint32_t ah[2][4], bh[4][4];
            // A hi fragments (2 m-tiles of 16)
            #pragma unroll
            for (int mt = 0; mt < 2; mt++)
                ldsm_x4(ah[mt][0], ah[mt][1], ah[mt][2], ah[mt][3],
                        sb + (uint32_t)((warp_m*32 + mt*16)*SROW) + lmOff + ko);
            // B hi fragments (4 x4 loads cover 8 n-tiles)
            #pragma unroll
            for (int bt = 0; bt < 4; bt++)
                ldsm_x4(bh[bt][0], bh[bt][1], bh[bt][2], bh[bt][3],
                        sb + 2*MAT_BYTES + (uint32_t)((warp_n*64 + bt*16)*SROW) + lmOff + ko);
            // Ahi * Bhi
            #pragma unroll
            for (int mt = 0; mt < 2; mt++)
                #pragma unroll
                for (int bt = 0; bt < 4; bt++){
                    mma_bf16(acc[mt][2*bt  ], ah[mt], bh[bt][0], bh[bt][2]);
                    mma_bf16(acc[mt][2*bt+1], ah[mt], bh[bt][1], bh[bt][3]);
                }
            // Alo * Bhi (alo transient)
            {
                uint32_t al[2][4];
                #pragma unroll
                for (int mt = 0; mt < 2; mt++)
                    ldsm_x4(al[mt][0], al[mt][1], al[mt][2], al[mt][3],
                            sb + MAT_BYTES + (uint32_t)((warp_m*32 + mt*16)*SROW) + lmOff + ko);
                #pragma unroll
                for (int mt = 0; mt < 2; mt++)
                    #pragma unroll
                    for (int bt = 0; bt < 4; bt++){
                        mma_bf16(acc[mt][2*bt  ], al[mt], bh[bt][0], bh[bt][2]);
                        mma_bf16(acc[mt][2*bt+1], al[mt], bh[bt][1], bh[bt][3]);
                    }
            }
            // Ahi * Blo (blo transient)
            {
                uint32_t bl[4][4];
                #pragma unroll
                for (int bt = 0; bt < 4; bt++)
                    ldsm_x4(bl[bt][0], bl[bt][1], bl[bt][2], bl[bt][3],
                            sb + 3*MAT_BYTES + (uint32_t)((warp_n*64 + bt*16)*SROW) + lmOff + ko);
                #pragma unroll
                for (int mt = 0; mt < 2; mt++)
                    #pragma unroll
                    for (int bt = 0; bt < 4; bt++){
                        mma_bf16(acc[mt][2*bt  ], ah[mt], bl[bt][0], bl[bt][2]);
                        mma_bf16(acc[mt][2*bt+1], ah[mt], bl[bt][1], bl[bt][3]);
                    }
            }
        }
        __syncthreads();
    }

    // ---- epilogue: scatter into sds time-planes ----
    const float cf = coeff[0];
    const int g4 = lane >> 2, t4 = lane & 3;
    const int tp = (n0 + warp_n*64) >> 6;                 // time plane for this warp
    #pragma unroll
    for (int mt = 0; mt < 2; mt++){
        int gm = m0 + warp_m*32 + mt*16 + g4;
        size_t rbase = OFF_SD + (size_t)tp*NH + (size_t)gm*64;
        #pragma unroll
        for (int nt = 0; nt < 8; nt++){
            int h = nt*8 + t4*2;
            out[rbase + h]          = cf*acc[mt][nt][0];
            out[rbase + h + 1]      = cf*acc[mt][nt][1];
            out[rbase + 512 + h]     = cf*acc[mt][nt][2];   // +8 rows = +8*64
            out[rbase + 512 + h + 1] = cf*acc[mt][nt][3];
        }
    }
}

// ---------------- launch ----------------
extern "C" void kernel_launch(void* const* d_in, const int* in_sizes, int n_in,
                              void* d_out, int out_size)
{
    (void)in_sizes; (void)n_in; (void)out_size;
    const float* node_attrs  = (const float*)d_in[0];
    const float* edge_attrs  = (const float*)d_in[1];
    const float* global_attr = (const float*)d_in[2];
    const float* sp_L        = (const float*)d_in[3];
    const float* coeff       = (const float*)d_in[4];
    const float* w_edge_enc  = (const float*)d_in[5];
    const float* b_edge_enc  = (const float*)d_in[6];
    const float* w_node_enc  = (const float*)d_in[7];
    const float* b_node_enc  = (const float*)d_in[8];
    const float* w_eb        = (const float*)d_in[9];
    const float* b_eb        = (const float*)d_in[10];
    const float* w_nb        = (const float*)d_in[11];
    const float* b_nb        = (const float*)d_in[12];
    const float* w_gb        = (const float*)d_in[13];
    const float* b_gb        = (const float*)d_in[14];
    const float* gru_w_ih    = (const float*)d_in[15];
    const float* gru_w_hh    = (const float*)d_in[16];
    const float* gru_b_ih    = (const float*)d_in[17];
    const float* gru_b_hh    = (const float*)d_in[18];
    const float* w_lout      = (const float*)d_in[19];
    const float* b_lout      = (const float*)d_in[20];
    const int*   edge_index  = (const int*)d_in[21];
    float* out = (float*)d_out;

    cudaFuncSetAttribute(tc_gemm_kernel, cudaFuncAttributeMaxDynamicSharedMemorySize, GSMEM_BYTES);

    prep_kernel<<<16, 256>>>(w_eb, w_nb, gru_w_hh);
    zero_kernel<<<2048, 256>>>();
    convA_kernel<<<65536, 256>>>(sp_L);
    gru_kernel<<<2048, 256>>>(node_attrs, gru_w_ih, gru_b_ih, gru_b_hh,
                              w_lout, b_lout, out);
    kernelD<<<1, 64>>>(1, global_attr, w_gb, b_gb, w_eb, b_eb, w_nb, b_nb);

    for (int t = 0; t < T_STEPS; t++){
        kernelA<<<512, 256>>>(t, node_attrs, w_node_enc, b_node_enc);
        kernelB<<<1024, 256>>>(t, edge_attrs, w_edge_enc, b_edge_enc, edge_index);
        kernelC<<<512, 256>>>(t, out);
        kernelD<<<1, 64>>>(0, global_attr, w_gb, b_gb, w_eb, b_eb, w_nb, b_nb);
    }

    convB_kernel<<<24576, 256>>>();
    dim3 grid(6, 64);   // 768/128 cols, 8192/128 rows
    tc_gemm_kernel<<<grid, 256, GSMEM_BYTES>>>(coeff, out);
}